// round 13
// baseline (speedup 1.0000x reference)
#include <cuda_runtime.h>
#include <cuda_bf16.h>
#include <cstdint>

// ---------------- problem constants ----------------
#define NIMG 32
#define CH   256
#define HH   36
#define WW   36
#define HWSZ 1296
#define MTOT (NIMG*HWSZ)   // 41472
#define KTOT (CH*9)        // 2304
#define NK2  (KTOT/2)      // 1152
#define NROI 512
#define FCK  4096
#define EPS_BN 1e-5f
#define CHW  (CH*HWSZ)

// ---------------- scratch ----------------
__device__ float g_bufA[MTOT*CH];           // conv output, NHWC fp32
__device__ uint2 g_aP [128*MTOT];           // activations [ci2][M] (hi bf16x2, lo bf16x2)
__device__ uint2 g_wbP[3*NK2*CH];           // weights [layer][k2][n] (hi, lo)
__device__ float g_ft [MTOT*CH];            // NHWC feat (pool phase)
__device__ float g_Ux [MTOT*CH];
__device__ float g_Uy [MTOT*CH];
__device__ float g_T  [MTOT*CH];
__device__ float g_rf [NROI*FCK];
__device__ float g_fc [NROI*CH];
__device__ float g_sum[3*CH], g_sq[3*CH];   // per-layer conv BN stats
__device__ float g_fsum[CH], g_fsq[CH];

// ---------------- helpers ----------------
__device__ __forceinline__ uint32_t smem_u32(const void* p) {
    uint32_t a;
    asm("{ .reg .u64 t; cvta.to.shared.u64 t, %1; cvt.u32.u64 %0, t; }" : "=r"(a) : "l"(p));
    return a;
}
__device__ __forceinline__ void bfsplit(float v, uint16_t& hi, uint16_t& lo) {
    __nv_bfloat16 h = __float2bfloat16(v);
    __nv_bfloat16 l = __float2bfloat16(v - __bfloat162float(h));
    hi = __bfloat16_as_ushort(h);
    lo = __bfloat16_as_ushort(l);
}
__device__ __forceinline__ void mma16(float d[4], const uint32_t a[4], const uint32_t b[2]) {
    asm volatile("mma.sync.aligned.m16n8k16.row.col.f32.bf16.bf16.f32 "
        "{%0,%1,%2,%3},{%4,%5,%6,%7},{%8,%9},{%0,%1,%2,%3};"
        : "+f"(d[0]), "+f"(d[1]), "+f"(d[2]), "+f"(d[3])
        : "r"(a[0]), "r"(a[1]), "r"(a[2]), "r"(a[3]), "r"(b[0]), "r"(b[1]));
}
__device__ __forceinline__ void cp8(uint32_t dst, const void* src, uint32_t sz) {
    asm volatile("cp.async.ca.shared.global [%0], [%1], 8, %2;" :: "r"(dst), "l"(src), "r"(sz));
}
__device__ __forceinline__ void cp16(uint32_t dst, const void* src) {
    asm volatile("cp.async.cg.shared.global [%0], [%1], 16;" :: "r"(dst), "l"(src));
}
#define CP_COMMIT() asm volatile("cp.async.commit_group;" ::: "memory")
#define CP_WAIT1()  asm volatile("cp.async.wait_group 1;"  ::: "memory")

// ---------------- weight prep for ALL 3 layers + stat zeroing ----------------
// grid 3*NK2 blocks x 256: layer = bx / NK2, idx = (bx % NK2)*256 + tid
__global__ void k_wprep3(const float* __restrict__ W1,
                         const float* __restrict__ W2,
                         const float* __restrict__ W3)
{
    const int layer = blockIdx.x / NK2;
    const int bx2   = blockIdx.x - layer * NK2;
    if (bx2 == 0) {
        g_sum[layer * CH + threadIdx.x] = 0.f;
        g_sq [layer * CH + threadIdx.x] = 0.f;
    }
    const float* W = (layer == 0) ? W1 : (layer == 1 ? W2 : W3);
    int idx = bx2 * 256 + threadIdx.x;          // idx = k2*256 + n
    int n   = idx & 255;
    int k2  = idx >> 8;
    int ci2 = k2 & 127;
    int tap = k2 >> 7;
    float v0 = __ldg(&W[(size_t)n * KTOT + (2 * ci2)     * 9 + tap]);
    float v1 = __ldg(&W[(size_t)n * KTOT + (2 * ci2 + 1) * 9 + tap]);
    uint16_t h0, l0, h1, l1;
    bfsplit(v0, h0, l0);
    bfsplit(v1, h1, l1);
    g_wbP[(size_t)layer * (NK2 * CH) + idx] =
        make_uint2(((uint32_t)h1 << 16) | h0, ((uint32_t)l1 << 16) | l0);
}

// ---------------- conv1 input prep: NCHW feat -> [ci2][M] packed uint2 ----------------
__global__ void k_cvtA(const float* __restrict__ feat) {
    int i   = blockIdx.x * 256 + threadIdx.x;   // i = ci2*MTOT + m
    int ci2 = i / MTOT;
    int m   = i - ci2 * MTOT;
    int nimg = m / HWSZ;
    int hw   = m - nimg * HWSZ;
    const size_t s = ((size_t)nimg * CH + 2 * ci2) * HWSZ + hw;
    float v0 = __ldg(&feat[s]);
    float v1 = __ldg(&feat[s + HWSZ]);
    uint16_t h0, l0, h1, l1;
    bfsplit(v0, h0, l0);
    bfsplit(v1, h1, l1);
    g_aP[i] = make_uint2(((uint32_t)h1 << 16) | h0, ((uint32_t)l1 << 16) | l0);
}

// ===== 3-stage pipelined bf16x3 m16n8k16 conv, packed (hi,lo) operands, 2 CTAs/SM =====
// CTA 128x128, 128 threads, warp tile 64x64; K = 72 chunks of 32 (16 k2).
// Stage: A[16 k2][132 uint2] + B[16 k2][132 uint2] = 33792 B; 3 stages = 101376 B.
#define NCHNK 72
#define STG_B 33792
#define STG_U 4224           // stage in uint2
#define ROWU  132            // row stride in uint2 (1056 B)

__global__ void __launch_bounds__(128, 2) k_conv_m(const float* __restrict__ bias, int layer)
{
    extern __shared__ uint2 dyn2[];
    __shared__ float sRed1[128], sRed2[128];
    const uint32_t sb = smem_u32(dyn2);

    const int tid  = threadIdx.x;
    const int lane = tid & 31, wid = tid >> 5;
    const int mt   = blockIdx.x * 128, nt = blockIdx.y * 128;
    const int wm   = (wid >> 1) * 64, wn = (wid & 1) * 64;
    const int g    = lane >> 2, c0 = lane & 3;

    sRed1[tid] = 0.f; sRed2[tid] = 0.f;

    // A-fill: thread owns m = mt + tid; 16 k2 per chunk, gmem stride MTOT
    const int mA    = mt + tid;
    const int nimgA = mA / HWSZ;
    const int remA  = mA - nimgA * HWSZ;
    const int hA    = remA / WW;
    const int wA    = remA - hA * WW;
    const int aimg  = nimgA * HWSZ;

    // B-fill: rows bkrow+4j, 2 n-slots (bn2, bn2+64)
    const int bkrow = tid >> 5;
    const int bn2   = (tid & 31) * 2;

    const uint2* Wp = g_wbP + (size_t)layer * (NK2 * CH);

    float acc[4][8][4];
#pragma unroll
    for (int a = 0; a < 4; ++a)
#pragma unroll
        for (int b = 0; b < 8; ++b)
#pragma unroll
            for (int c = 0; c < 4; ++c) acc[a][b][c] = 0.f;

    auto fillA = [&](int st, int ch) {
        const int tap = ch >> 3, cc = ch & 7;
        const int hh = hA + tap / 3 - 1, ww = wA + tap % 3 - 1;
        const bool valid = ((unsigned)hh < HH) && ((unsigned)ww < WW);
        const uint32_t sz = valid ? 8u : 0u;
        const uint2* p = g_aP + (size_t)(cc * 16) * MTOT + aimg + (valid ? hh * WW + ww : 0);
        uint32_t d = sb + st * STG_B + tid * 8;
#pragma unroll
        for (int i = 0; i < 16; ++i) {
            cp8(d, p, sz);
            p += MTOT; d += 1056;
        }
    };
    auto fillB = [&](int st, int ch) {
        const int tap = ch >> 3, cc = ch & 7;
        const int kb2 = tap * 128 + cc * 16;
        uint32_t d = sb + st * STG_B + 16896 + bkrow * 1056 + bn2 * 8;
#pragma unroll
        for (int j = 0; j < 4; ++j) {
            const uint2* src = Wp + (size_t)(kb2 + bkrow + j * 4) * 256 + nt + bn2;
            cp16(d + j * 4224,       src);
            cp16(d + j * 4224 + 512, src + 64);
        }
    };

    // prologue: stages 0 and 1 (chunks 0 and 1)
    fillA(0, 0); fillB(0, 0); CP_COMMIT();
    fillA(1, 1); fillB(1, 1); CP_COMMIT();

    int stc = 0, stf = 2;
    for (int ch = 0; ch < NCHNK; ++ch) {
        CP_WAIT1();
        __syncthreads();
        const bool pf = (ch + 2) < NCHNK;
        const uint2* As = dyn2 + stc * STG_U;
        const uint2* Bs = As + 2112;
#pragma unroll
        for (int kk = 0; kk < 2; ++kk) {
            if (pf) {
                if (kk == 0) fillA(stf, ch + 2);
                else         fillB(stf, ch + 2);
            }
            const int r0 = (kk * 8 + c0) * ROWU;
            const int r1 = r0 + 4 * ROWU;
            uint32_t ah[4][4], al[4][4], bh[8][2], bl[8][2];
#pragma unroll
            for (int mf = 0; mf < 4; ++mf) {
                const int col = wm + mf * 16 + g;
                uint2 v0 = As[r0 + col];
                uint2 v1 = As[r0 + col + 8];
                uint2 v2 = As[r1 + col];
                uint2 v3 = As[r1 + col + 8];
                ah[mf][0] = v0.x; ah[mf][1] = v1.x; ah[mf][2] = v2.x; ah[mf][3] = v3.x;
                al[mf][0] = v0.y; al[mf][1] = v1.y; al[mf][2] = v2.y; al[mf][3] = v3.y;
            }
#pragma unroll
            for (int nf = 0; nf < 8; ++nf) {
                const int q0 = r0 + wn + nf * 8 + g;
                uint2 w0 = Bs[q0];
                uint2 w1 = Bs[q0 + 4 * ROWU];
                bh[nf][0] = w0.x; bh[nf][1] = w1.x;
                bl[nf][0] = w0.y; bl[nf][1] = w1.y;
            }
#pragma unroll
            for (int mf = 0; mf < 4; ++mf)
#pragma unroll
                for (int nf = 0; nf < 8; ++nf)
                    mma16(acc[mf][nf], ah[mf], bh[nf]);
#pragma unroll
            for (int mf = 0; mf < 4; ++mf)
#pragma unroll
                for (int nf = 0; nf < 8; ++nf)
                    mma16(acc[mf][nf], ah[mf], bl[nf]);
#pragma unroll
            for (int mf = 0; mf < 4; ++mf)
#pragma unroll
                for (int nf = 0; nf < 8; ++nf)
                    mma16(acc[mf][nf], al[mf], bh[nf]);
        }
        CP_COMMIT();
        stc = (stc == 2) ? 0 : stc + 1;
        stf = (stf == 2) ? 0 : stf + 1;
    }

    // ---------------- epilogue: bias, NHWC store, fused stats ----------------
    float s1[16], s2[16];
#pragma unroll
    for (int i = 0; i < 16; ++i) { s1[i] = 0.f; s2[i] = 0.f; }

#pragma unroll
    for (int mf = 0; mf < 4; ++mf) {
#pragma unroll
        for (int rr = 0; rr < 2; ++rr) {
            const int m = mt + wm + mf * 16 + g + rr * 8;
            float* orow = g_bufA + (size_t)m * CH;
#pragma unroll
            for (int nf = 0; nf < 8; ++nf) {
                const int c = nt + wn + nf * 8 + c0 * 2;
                const float v0 = acc[mf][nf][rr * 2]     + __ldg(&bias[c]);
                const float v1 = acc[mf][nf][rr * 2 + 1] + __ldg(&bias[c + 1]);
                *(float2*)(orow + c) = make_float2(v0, v1);
                s1[nf * 2]     += v0; s2[nf * 2]     += v0 * v0;
                s1[nf * 2 + 1] += v1; s2[nf * 2 + 1] += v1 * v1;
            }
        }
    }
    __syncthreads();
#pragma unroll
    for (int nf = 0; nf < 8; ++nf) {
        const int cl = wn + nf * 8 + c0 * 2;
        atomicAdd(&sRed1[cl],     s1[nf * 2]);
        atomicAdd(&sRed2[cl],     s2[nf * 2]);
        atomicAdd(&sRed1[cl + 1], s1[nf * 2 + 1]);
        atomicAdd(&sRed2[cl + 1], s2[nf * 2 + 1]);
    }
    __syncthreads();
    atomicAdd(&g_sum[layer * CH + nt + tid], sRed1[tid]);
    atomicAdd(&g_sq [layer * CH + nt + tid], sRed2[tid]);
}

// ---------------- BN+ReLU+split via 32x32 smem transpose: NHWC -> [ci2][M] packed ----------------
__global__ void k_bnsplit_t(const float* __restrict__ gm,
                            const float* __restrict__ bt, int layer)
{
    __shared__ float s[32][33];
    __shared__ float ssc[32], ssh[32];
    const int cb = blockIdx.x;
    const int n  = blockIdx.y;
    const int pb = blockIdx.z;
    const int tx = threadIdx.x, ty = threadIdx.y;
    const int tid = ty * 32 + tx;
    const float invN = 1.0f / (float)MTOT;

    if (tid < 32) {
        const int c = cb * 32 + tid;
        float m = g_sum[layer * CH + c] * invN;
        float v = g_sq[layer * CH + c] * invN - m * m;
        float sc = rsqrtf(v + EPS_BN) * __ldg(&gm[c]);
        ssc[tid] = sc;
        ssh[tid] = __ldg(&bt[c]) - m * sc;
    }
    __syncthreads();

    const int p0 = pb * 32;
#pragma unroll
    for (int yy = 0; yy < 4; ++yy) {
        const int p = p0 + ty + yy * 8;
        float x = (p < HWSZ)
                ? g_bufA[((size_t)n * HWSZ + p) * CH + cb * 32 + tx] : 0.f;
        s[tx][ty + yy * 8] = fmaxf(fmaf(x, ssc[tx], ssh[tx]), 0.f);
    }
    __syncthreads();
#pragma unroll
    for (int yy = 0; yy < 2; ++yy) {
        const int ci2l = ty + yy * 8;
        const int p = p0 + tx;
        if (p < HWSZ) {
            float y0 = s[2 * ci2l][tx];
            float y1 = s[2 * ci2l + 1][tx];
            uint16_t h0, l0, h1, l1;
            bfsplit(y0, h0, l0);
            bfsplit(y1, h1, l1);
            const size_t i = (size_t)(cb * 16 + ci2l) * MTOT + (size_t)n * HWSZ + p;
            g_aP[i] = make_uint2(((uint32_t)h1 << 16) | h0, ((uint32_t)l1 << 16) | l0);
        }
    }
}

// ---------------- fused final BN + ReLU + cumtrapz along w (layer 2 stats) ----------------
__global__ void k_bn_cumx(const float* __restrict__ gm,
                          const float* __restrict__ bt)
{
    const int nh = blockIdx.x;
    const int c  = threadIdx.x;
    const float invN = 1.0f / (float)MTOT;
    float m  = g_sum[2 * CH + c] * invN;
    float v  = g_sq[2 * CH + c] * invN - m * m;
    float sc = rsqrtf(v + EPS_BN) * __ldg(&gm[c]);
    float sh = __ldg(&bt[c]) - m * sc;

    size_t base = ((size_t)nh * WW) * CH + c;
    float prev = fmaxf(fmaf(g_bufA[base], sc, sh), 0.f);
    g_ft[base] = prev;
    g_Ux[base] = 0.f;
    float u = 0.f;
    for (int w = 1; w < WW; ++w) {
        float f = fmaxf(fmaf(g_bufA[base + (size_t)w * CH], sc, sh), 0.f);
        u += 0.5f * (prev + f);
        g_ft[base + (size_t)w * CH] = f;
        g_Ux[base + (size_t)w * CH] = u;
        prev = f;
    }
}

// ---------------- cumtrapz along h ----------------
__global__ void k_cumy()
{
    const int nw = blockIdx.x;
    const int n  = nw / WW;
    const int w  = nw - n * WW;
    const int c  = threadIdx.x;
    size_t base   = ((size_t)n * HWSZ + w) * CH + c;
    size_t stride = (size_t)WW * CH;
    float pf = g_ft[base], pu = g_Ux[base];
    float uy = 0.f, tt = 0.f;
    g_Uy[base] = 0.f;
    g_T[base]  = 0.f;
    for (int hh = 1; hh < HH; ++hh) {
        float f = g_ft[base + hh * stride];
        float u = g_Ux[base + hh * stride];
        uy += 0.5f * (pf + f);
        tt += 0.5f * (pu + u);
        g_Uy[base + hh * stride] = uy;
        g_T [base + hh * stride] = tt;
        pf = f; pu = u;
    }
}

// ---------------- PrRoI pooling (+ FC-stat zeroing + g_fc zeroing) ----------------
__global__ void k_pool(const float* __restrict__ props)
{
    const int p = blockIdx.x;
    const int c = threadIdx.x;
    if (p == 0) { g_fsum[c] = 0.f; g_fsq[c] = 0.f; }
    g_fc[(size_t)p * CH + c] = 0.f;     // zero for split-K fc atomics
    const float px = __ldg(&props[p * 4 + 0]);
    const float py = __ldg(&props[p * 4 + 1]);
    const float pw = __ldg(&props[p * 4 + 2]);
    const float ph = __ldg(&props[p * 4 + 3]);
    const float x1 = px * 20.f;
    const float y1 = py * 20.f;
    const float x2 = (px + pw) * 20.f;
    const float y2 = (py + ph) * 20.f;
    const float bw = (x2 - x1) * 0.25f;
    const float bh = (y2 - y1) * 0.25f;

    int   wx[5], hy[5];
    float px0[5], px1[5], py0[5], py1[5];
#pragma unroll
    for (int i = 0; i < 5; ++i) {
        float xs = fminf(fmaxf(x1 + bw * (float)i, 0.f), 35.f);
        int w0 = min((int)floorf(xs), 34);
        float sx = xs - (float)w0;
        float q = 0.5f * sx * sx;
        px1[i] = q; px0[i] = sx - q; wx[i] = w0;

        float ys = fminf(fmaxf(y1 + bh * (float)i, 0.f), 35.f);
        int h0 = min((int)floorf(ys), 34);
        float sy = ys - (float)h0;
        float r = 0.5f * sy * sy;
        py1[i] = r; py0[i] = sy - r; hy[i] = h0;
    }

    const int b = p >> 4;
    float G[5][5];
#pragma unroll
    for (int iy = 0; iy < 5; ++iy) {
#pragma unroll
        for (int ix = 0; ix < 5; ++ix) {
            size_t i00 = (((size_t)b * HH + hy[iy]) * WW + wx[ix]) * CH + c;
            size_t i01 = i00 + CH;
            size_t i10 = i00 + (size_t)WW * CH;
            size_t i11 = i10 + CH;
            G[iy][ix] = g_T[i00]
                      + g_Uy[i00] * px0[ix] + g_Uy[i01] * px1[ix]
                      + py0[iy] * (g_Ux[i00] + g_ft[i00] * px0[ix] + g_ft[i01] * px1[ix])
                      + py1[iy] * (g_Ux[i10] + g_ft[i10] * px0[ix] + g_ft[i11] * px1[ix]);
        }
    }
    const float area = bw * bh;
    const float inv  = (area > 1e-8f) ? (1.f / fmaxf(area, 1e-8f)) : 0.f;
    float* out = g_rf + (size_t)p * FCK + c * 16;
#pragma unroll
    for (int iy = 0; iy < 4; ++iy)
#pragma unroll
        for (int ix = 0; ix < 4; ++ix)
            out[iy * 4 + ix] =
                (G[iy + 1][ix + 1] - G[iy][ix + 1] - G[iy + 1][ix] + G[iy][ix]) * inv;
}

// ---------------- FC GEMM, split-K=8, atomic accumulate ----------------
__global__ void __launch_bounds__(256) k_fc(const float* __restrict__ Wfc)
{
    __shared__ float As[16][65];
    __shared__ float Bs[16][65];

    const int tid = threadIdx.x;
    const int mt  = blockIdx.x * 64;
    const int nt  = blockIdx.y * 64;
    const int kc0 = blockIdx.z * 32;      // 32 of 256 kc iterations
    const int lr  = tid >> 2;
    const int lk  = (tid & 3) * 4;
    const int tm  = tid & 15;
    const int tn  = tid >> 4;

    float acc[4][4];
#pragma unroll
    for (int i = 0; i < 4; ++i)
#pragma unroll
        for (int j = 0; j < 4; ++j) acc[i][j] = 0.f;

    for (int kc = kc0; kc < kc0 + 32; ++kc) {
        float4 av = *(const float4*)&g_rf[(size_t)(mt + lr) * FCK + kc * 16 + lk];
        float4 bv = *(const float4*)&Wfc [(size_t)(nt + lr) * FCK + kc * 16 + lk];
        __syncthreads();
        As[lk + 0][lr] = av.x; As[lk + 1][lr] = av.y;
        As[lk + 2][lr] = av.z; As[lk + 3][lr] = av.w;
        Bs[lk + 0][lr] = bv.x; Bs[lk + 1][lr] = bv.y;
        Bs[lk + 2][lr] = bv.z; Bs[lk + 3][lr] = bv.w;
        __syncthreads();
#pragma unroll
        for (int kk = 0; kk < 16; ++kk) {
            float a[4], b[4];
#pragma unroll
            for (int i = 0; i < 4; ++i) a[i] = As[kk][tm + 16 * i];
#pragma unroll
            for (int j = 0; j < 4; ++j) b[j] = Bs[kk][tn * 4 + j];
#pragma unroll
            for (int i = 0; i < 4; ++i)
#pragma unroll
                for (int j = 0; j < 4; ++j)
                    acc[i][j] = fmaf(a[i], b[j], acc[i][j]);
        }
    }
#pragma unroll
    for (int j = 0; j < 4; ++j) {
        const int c = nt + tn * 4 + j;
#pragma unroll
        for (int i = 0; i < 4; ++i) {
            const int m = mt + tm + 16 * i;
            atomicAdd(&g_fc[(size_t)m * CH + c], acc[i][j]);
        }
    }
}

// ---------------- FC bias + stats ----------------
// grid 32 blocks x 256 thr: block handles 16 rows; thread = channel.
__global__ void k_fcstat(const float* __restrict__ fcb)
{
    const int c = threadIdx.x;
    const float b = __ldg(&fcb[c]);
    float s1 = 0.f, s2 = 0.f;
#pragma unroll
    for (int r = 0; r < 16; ++r) {
        const int row = blockIdx.x * 16 + r;
        float v = g_fc[(size_t)row * CH + c] + b;
        g_fc[(size_t)row * CH + c] = v;
        s1 += v; s2 += v * v;
    }
    atomicAdd(&g_fsum[c], s1);
    atomicAdd(&g_fsq [c], s2);
}

// ---------------- FC BN + ReLU + IoU head ----------------
__global__ void k_fcbn_iou(const float* __restrict__ gm,
                           const float* __restrict__ bt,
                           const float* __restrict__ iw,
                           const float* __restrict__ ib,
                           float* __restrict__ out)
{
    __shared__ float sred[8];
    const int p = blockIdx.x;
    const int c = threadIdx.x;
    const float invN = 1.f / (float)NROI;
    float m  = g_fsum[c] * invN;
    float v  = g_fsq[c] * invN - m * m;
    float sc = rsqrtf(v + EPS_BN) * __ldg(&gm[c]);
    float sh = __ldg(&bt[c]) - m * sc;
    float x  = fmaxf(fmaf(g_fc[(size_t)p * CH + c], sc, sh), 0.f);
    float t  = x * __ldg(&iw[c]);
#pragma unroll
    for (int o = 16; o; o >>= 1) t += __shfl_xor_sync(0xffffffffu, t, o);
    if ((c & 31) == 0) sred[c >> 5] = t;
    __syncthreads();
    if (c == 0) {
        float s = 0.f;
#pragma unroll
        for (int i = 0; i < 8; ++i) s += sred[i];
        out[p] = s + __ldg(&ib[0]);
    }
}

// ---------------- launch sequence ----------------
extern "C" void kernel_launch(void* const* d_in, const int* in_sizes, int n_in,
                              void* d_out, int out_size)
{
    const float* feat  = (const float*)d_in[0];
    const float* props = (const float*)d_in[1];
    const float* c1w = (const float*)d_in[2];
    const float* c1b = (const float*)d_in[3];
    const float* b1g = (const float*)d_in[4];
    const float* b1b = (const float*)d_in[5];
    const float* c2w = (const float*)d_in[6];
    const float* c2b = (const float*)d_in[7];
    const float* b2g = (const float*)d_in[8];
    const float* b2b = (const float*)d_in[9];
    const float* c3w = (const float*)d_in[10];
    const float* c3b = (const float*)d_in[11];
    const float* b3g = (const float*)d_in[12];
    const float* b3b = (const float*)d_in[13];
    const float* fcw = (const float*)d_in[14];
    const float* fcb = (const float*)d_in[15];
    const float* fbg = (const float*)d_in[16];
    const float* fbb = (const float*)d_in[17];
    const float* iw  = (const float*)d_in[18];
    const float* ib  = (const float*)d_in[19];
    float* out = (float*)d_out;

    const int CONV_SMEM = 3 * STG_B;   // 101376 B per CTA, 2 CTAs/SM
    cudaFuncSetAttribute(k_conv_m, cudaFuncAttributeMaxDynamicSharedMemorySize, CONV_SMEM);

    const dim3 convGrid(MTOT / 128, 2);
    const int  spBlocks = 128 * MTOT / 256;     // 20736 (cvtA)

    // all weight preps + per-layer stat zeroing in one launch
    k_wprep3<<<3 * NK2, 256>>>(c1w, c2w, c3w);
    k_cvtA<<<spBlocks, 256>>>(feat);

    // conv1
    k_conv_m<<<convGrid, 128, CONV_SMEM>>>(c1b, 0);
    k_bnsplit_t<<<dim3(8, NIMG, 41), dim3(32, 8)>>>(b1g, b1b, 0);
    // conv2
    k_conv_m<<<convGrid, 128, CONV_SMEM>>>(c2b, 1);
    k_bnsplit_t<<<dim3(8, NIMG, 41), dim3(32, 8)>>>(b2g, b2b, 1);
    // conv3
    k_conv_m<<<convGrid, 128, CONV_SMEM>>>(c3b, 2);

    // fused final BN + cumx, then cumy (integral images, NHWC)
    k_bn_cumx<<<NIMG * HH, 256>>>(b3g, b3b);
    k_cumy<<<NIMG * WW, 256>>>();

    // PrRoI pooling (zeroes FC stats + g_fc)
    k_pool<<<NROI, 256>>>(props);

    // FC (split-K) + bias/stats + BN + IoU
    k_fc<<<dim3(NROI / 64, CH / 64, 8), 256>>>(fcw);
    k_fcstat<<<32, 256>>>(fcb);
    k_fcbn_iou<<<NROI, 256>>>(fbg, fbb, iw, ib, out);
}

// round 14
// speedup vs baseline: 1.3331x; 1.3331x over previous
#include <cuda_runtime.h>
#include <cuda_bf16.h>
#include <cstdint>

// ---------------- problem constants ----------------
#define NIMG 32
#define CH   256
#define HH   36
#define WW   36
#define HWSZ 1296
#define MTOT (NIMG*HWSZ)   // 41472
#define KTOT (CH*9)        // 2304
#define NK2  (KTOT/2)      // 1152
#define NROI 512
#define FCK  4096
#define EPS_BN 1e-5f
#define CHW  (CH*HWSZ)

// ---------------- scratch ----------------
__device__ float    g_bufA[MTOT*CH];        // conv output, NHWC fp32
__device__ uint32_t g_aH[128*MTOT];         // activations [ci2][M] bf16x2 hi
__device__ uint32_t g_aL[128*MTOT];         // lo residual
__device__ uint32_t g_wbH[NK2*CH];          // weights [k2][n] bf16x2 hi (k = tap*256+ci)
__device__ uint32_t g_wbL[NK2*CH];
__device__ float g_ft [MTOT*CH];            // NHWC feat (pool phase)
__device__ float g_Ux [MTOT*CH];
__device__ float g_Uy [MTOT*CH];
__device__ float g_T  [MTOT*CH];
__device__ float g_rf [NROI*FCK];
__device__ float g_fc [NROI*CH];
__device__ float g_sum[CH], g_sq[CH];
__device__ float g_fsum[CH], g_fsq[CH];

// ---------------- helpers ----------------
__device__ __forceinline__ uint32_t smem_u32(const void* p) {
    uint32_t a;
    asm("{ .reg .u64 t; cvta.to.shared.u64 t, %1; cvt.u32.u64 %0, t; }" : "=r"(a) : "l"(p));
    return a;
}
__device__ __forceinline__ void bfsplit(float v, uint16_t& hi, uint16_t& lo) {
    __nv_bfloat16 h = __float2bfloat16(v);
    __nv_bfloat16 l = __float2bfloat16(v - __bfloat162float(h));
    hi = __bfloat16_as_ushort(h);
    lo = __bfloat16_as_ushort(l);
}
__device__ __forceinline__ void mma16(float d[4], const uint32_t a[4], const uint32_t b[2]) {
    asm volatile("mma.sync.aligned.m16n8k16.row.col.f32.bf16.bf16.f32 "
        "{%0,%1,%2,%3},{%4,%5,%6,%7},{%8,%9},{%0,%1,%2,%3};"
        : "+f"(d[0]), "+f"(d[1]), "+f"(d[2]), "+f"(d[3])
        : "r"(a[0]), "r"(a[1]), "r"(a[2]), "r"(a[3]), "r"(b[0]), "r"(b[1]));
}
__device__ __forceinline__ void cp4(uint32_t dst, const void* src, uint32_t sz) {
    asm volatile("cp.async.ca.shared.global [%0], [%1], 4, %2;" :: "r"(dst), "l"(src), "r"(sz));
}
__device__ __forceinline__ void cp16(uint32_t dst, const void* src) {
    asm volatile("cp.async.cg.shared.global [%0], [%1], 16;" :: "r"(dst), "l"(src));
}
#define CP_COMMIT() asm volatile("cp.async.commit_group;" ::: "memory")
#define CP_WAIT1()  asm volatile("cp.async.wait_group 1;"  ::: "memory")

// ---------------- weight prep: [k2][n] bf16-pair split + conv-stat zeroing ----------------
__global__ void k_wprep(const float* __restrict__ W) {
    int idx = blockIdx.x * 256 + threadIdx.x;   // idx = k2*256 + n
    if (blockIdx.x == 0) {
        g_sum[threadIdx.x] = 0.f;
        g_sq [threadIdx.x] = 0.f;
    }
    int n   = idx & 255;
    int k2  = idx >> 8;
    int ci2 = k2 & 127;
    int tap = k2 >> 7;
    float v0 = __ldg(&W[(size_t)n * KTOT + (2 * ci2)     * 9 + tap]);
    float v1 = __ldg(&W[(size_t)n * KTOT + (2 * ci2 + 1) * 9 + tap]);
    uint16_t h0, l0, h1, l1;
    bfsplit(v0, h0, l0);
    bfsplit(v1, h1, l1);
    g_wbH[idx] = ((uint32_t)h1 << 16) | h0;
    g_wbL[idx] = ((uint32_t)l1 << 16) | l0;
}

// ---------------- conv1 input prep: NCHW feat -> [ci2][M] bf16-pair split ----------------
__global__ void k_cvtA(const float* __restrict__ feat) {
    int i   = blockIdx.x * 256 + threadIdx.x;   // i = ci2*MTOT + m
    int ci2 = i / MTOT;
    int m   = i - ci2 * MTOT;
    int nimg = m / HWSZ;
    int hw   = m - nimg * HWSZ;
    const size_t s = ((size_t)nimg * CH + 2 * ci2) * HWSZ + hw;
    float v0 = __ldg(&feat[s]);
    float v1 = __ldg(&feat[s + HWSZ]);
    uint16_t h0, l0, h1, l1;
    bfsplit(v0, h0, l0);
    bfsplit(v1, h1, l1);
    g_aH[i] = ((uint32_t)h1 << 16) | h0;
    g_aL[i] = ((uint32_t)l1 << 16) | l0;
}

// ===== 3-stage pipelined bf16x3 m16n8k16 implicit-GEMM conv, 2 CTAs/SM =====
#define NCHNK 72
#define STG_W 8704           // stage size in words
#define STG_B 34816          // stage size in bytes

__global__ void __launch_bounds__(128, 2) k_conv_m(const float* __restrict__ bias)
{
    extern __shared__ uint32_t dynu[];
    __shared__ float sRed1[128], sRed2[128];
    const uint32_t sb = smem_u32(dynu);

    const int tid  = threadIdx.x;
    const int lane = tid & 31, wid = tid >> 5;
    const int mt   = blockIdx.x * 128, nt = blockIdx.y * 128;
    const int wm   = (wid >> 1) * 64, wn = (wid & 1) * 64;
    const int g    = lane >> 2, c0 = lane & 3;

    sRed1[tid] = 0.f; sRed2[tid] = 0.f;

    // A-fill mapping: thread owns m = mt + tid; 16 k2 per chunk, stride MTOT
    const int mA    = mt + tid;
    const int nimgA = mA / HWSZ;
    const int remA  = mA - nimgA * HWSZ;
    const int hA    = remA / WW;
    const int wA    = remA - hA * WW;
    const int aimg  = nimgA * HWSZ;

    // B-fill mapping: rows bkrow+4j, 16B of n
    const int bkrow = tid >> 5;            // 0..3
    const int bn4   = (tid & 31) * 4;      // word offset in n

    float acc[4][8][4];
#pragma unroll
    for (int a = 0; a < 4; ++a)
#pragma unroll
        for (int b = 0; b < 8; ++b)
#pragma unroll
            for (int c = 0; c < 4; ++c) acc[a][b][c] = 0.f;

    auto fillA = [&](int st, int ch, int half) {
        const int tap = ch >> 3, cc = ch & 7;
        const int hh = hA + tap / 3 - 1, ww = wA + tap % 3 - 1;
        const bool valid = ((unsigned)hh < HH) && ((unsigned)ww < WW);
        const uint32_t sz = valid ? 4u : 0u;
        const uint32_t* p = (half ? g_aL : g_aH)
                          + (size_t)(cc * 16) * MTOT + aimg + (valid ? hh * WW + ww : 0);
        uint32_t d = sb + st * STG_B + half * 8704 + tid * 4;
#pragma unroll
        for (int i = 0; i < 16; ++i) {
            cp4(d, p, sz);
            p += MTOT; d += 544;
        }
    };
    auto fillB = [&](int st, int ch, int half) {
        const int tap = ch >> 3, cc = ch & 7;
        const int kb2 = tap * 128 + cc * 16;
        const uint32_t* Wp = half ? g_wbL : g_wbH;
        uint32_t d = sb + st * STG_B + 17408 + half * 8704 + bkrow * 544 + bn4 * 4;
#pragma unroll
        for (int j = 0; j < 4; ++j)
            cp16(d + j * 2176, Wp + (size_t)(kb2 + bkrow + j * 4) * 256 + nt + bn4);
    };

    // prologue: stages 0 and 1 (chunks 0 and 1)
    fillA(0, 0, 0); fillA(0, 0, 1); fillB(0, 0, 0); fillB(0, 0, 1); CP_COMMIT();
    fillA(1, 1, 0); fillA(1, 1, 1); fillB(1, 1, 0); fillB(1, 1, 1); CP_COMMIT();

    int stc = 0, stf = 2;
    for (int ch = 0; ch < NCHNK; ++ch) {
        CP_WAIT1();
        __syncthreads();
        const bool pf = (ch + 2) < NCHNK;
        const uint32_t* base = dynu + stc * STG_W;
        const uint32_t* AsH = base;
        const uint32_t* AsL = base + 2176;
        const uint32_t* BsH = base + 4352;
        const uint32_t* BsL = base + 6528;
#pragma unroll
        for (int kk = 0; kk < 2; ++kk) {
            if (pf) {
                if (kk == 0) { fillA(stf, ch + 2, 0); fillA(stf, ch + 2, 1); }
                else         { fillB(stf, ch + 2, 0); fillB(stf, ch + 2, 1); }
            }
            const int r0 = (kk * 8 + c0) * 136;
            const int r1 = r0 + 4 * 136;
            uint32_t ah[4][4], al[4][4], bh[8][2], bl[8][2];
#pragma unroll
            for (int mf = 0; mf < 4; ++mf) {
                const int col = wm + mf * 16 + g;
                ah[mf][0] = AsH[r0 + col];
                ah[mf][1] = AsH[r0 + col + 8];
                ah[mf][2] = AsH[r1 + col];
                ah[mf][3] = AsH[r1 + col + 8];
                al[mf][0] = AsL[r0 + col];
                al[mf][1] = AsL[r0 + col + 8];
                al[mf][2] = AsL[r1 + col];
                al[mf][3] = AsL[r1 + col + 8];
            }
#pragma unroll
            for (int nf = 0; nf < 8; ++nf) {
                const int q0 = r0 + wn + nf * 8 + g;
                const int q1 = q0 + 4 * 136;
                bh[nf][0] = BsH[q0];
                bh[nf][1] = BsH[q1];
                bl[nf][0] = BsL[q0];
                bl[nf][1] = BsL[q1];
            }
#pragma unroll
            for (int mf = 0; mf < 4; ++mf)
#pragma unroll
                for (int nf = 0; nf < 8; ++nf)
                    mma16(acc[mf][nf], ah[mf], bh[nf]);
#pragma unroll
            for (int mf = 0; mf < 4; ++mf)
#pragma unroll
                for (int nf = 0; nf < 8; ++nf)
                    mma16(acc[mf][nf], ah[mf], bl[nf]);
#pragma unroll
            for (int mf = 0; mf < 4; ++mf)
#pragma unroll
                for (int nf = 0; nf < 8; ++nf)
                    mma16(acc[mf][nf], al[mf], bh[nf]);
        }
        CP_COMMIT();
        stc = (stc == 2) ? 0 : stc + 1;
        stf = (stf == 2) ? 0 : stf + 1;
    }

    // ---------------- epilogue: bias, NHWC store (coalesced), fused stats ----------------
    float s1[16], s2[16];
#pragma unroll
    for (int i = 0; i < 16; ++i) { s1[i] = 0.f; s2[i] = 0.f; }

#pragma unroll
    for (int mf = 0; mf < 4; ++mf) {
#pragma unroll
        for (int rr = 0; rr < 2; ++rr) {
            const int m = mt + wm + mf * 16 + g + rr * 8;
            float* orow = g_bufA + (size_t)m * CH;
#pragma unroll
            for (int nf = 0; nf < 8; ++nf) {
                const int c = nt + wn + nf * 8 + c0 * 2;
                const float v0 = acc[mf][nf][rr * 2]     + __ldg(&bias[c]);
                const float v1 = acc[mf][nf][rr * 2 + 1] + __ldg(&bias[c + 1]);
                *(float2*)(orow + c) = make_float2(v0, v1);
                s1[nf * 2]     += v0; s2[nf * 2]     += v0 * v0;
                s1[nf * 2 + 1] += v1; s2[nf * 2 + 1] += v1 * v1;
            }
        }
    }
    __syncthreads();
#pragma unroll
    for (int nf = 0; nf < 8; ++nf) {
        const int cl = wn + nf * 8 + c0 * 2;
        atomicAdd(&sRed1[cl],     s1[nf * 2]);
        atomicAdd(&sRed2[cl],     s2[nf * 2]);
        atomicAdd(&sRed1[cl + 1], s1[nf * 2 + 1]);
        atomicAdd(&sRed2[cl + 1], s2[nf * 2 + 1]);
    }
    __syncthreads();
    atomicAdd(&g_sum[nt + tid], sRed1[tid]);
    atomicAdd(&g_sq [nt + tid], sRed2[tid]);
}

// ---------------- BN+ReLU+split via 32x32 smem transpose: NHWC -> [ci2][M] ----------------
__global__ void k_bnsplit_t(const float* __restrict__ gm,
                            const float* __restrict__ bt)
{
    __shared__ float s[32][33];
    __shared__ float ssc[32], ssh[32];
    const int cb = blockIdx.x;
    const int n  = blockIdx.y;
    const int pb = blockIdx.z;
    const int tx = threadIdx.x, ty = threadIdx.y;
    const int tid = ty * 32 + tx;
    const float invN = 1.0f / (float)MTOT;

    if (tid < 32) {
        const int c = cb * 32 + tid;
        float m = g_sum[c] * invN;
        float v = g_sq[c] * invN - m * m;
        float sc = rsqrtf(v + EPS_BN) * __ldg(&gm[c]);
        ssc[tid] = sc;
        ssh[tid] = __ldg(&bt[c]) - m * sc;
    }
    __syncthreads();

    const int p0 = pb * 32;
#pragma unroll
    for (int yy = 0; yy < 4; ++yy) {
        const int p = p0 + ty + yy * 8;
        float x = (p < HWSZ)
                ? g_bufA[((size_t)n * HWSZ + p) * CH + cb * 32 + tx] : 0.f;
        s[tx][ty + yy * 8] = fmaxf(fmaf(x, ssc[tx], ssh[tx]), 0.f);
    }
    __syncthreads();
#pragma unroll
    for (int yy = 0; yy < 2; ++yy) {
        const int ci2l = ty + yy * 8;       // 0..15
        const int p = p0 + tx;
        if (p < HWSZ) {
            float y0 = s[2 * ci2l][tx];
            float y1 = s[2 * ci2l + 1][tx];
            uint16_t h0, l0, h1, l1;
            bfsplit(y0, h0, l0);
            bfsplit(y1, h1, l1);
            const size_t i = (size_t)(cb * 16 + ci2l) * MTOT + (size_t)n * HWSZ + p;
            g_aH[i] = ((uint32_t)h1 << 16) | h0;
            g_aL[i] = ((uint32_t)l1 << 16) | l0;
        }
    }
}

// ---------------- fused final BN + ReLU + cumtrapz along w ----------------
__global__ void k_bn_cumx(const float* __restrict__ gm,
                          const float* __restrict__ bt)
{
    const int nh = blockIdx.x;
    const int c  = threadIdx.x;
    const float invN = 1.0f / (float)MTOT;
    float m  = g_sum[c] * invN;
    float v  = g_sq[c] * invN - m * m;
    float sc = rsqrtf(v + EPS_BN) * __ldg(&gm[c]);
    float sh = __ldg(&bt[c]) - m * sc;

    size_t base = ((size_t)nh * WW) * CH + c;
    float prev = fmaxf(fmaf(g_bufA[base], sc, sh), 0.f);
    g_ft[base] = prev;
    g_Ux[base] = 0.f;
    float u = 0.f;
    for (int w = 1; w < WW; ++w) {
        float f = fmaxf(fmaf(g_bufA[base + (size_t)w * CH], sc, sh), 0.f);
        u += 0.5f * (prev + f);
        g_ft[base + (size_t)w * CH] = f;
        g_Ux[base + (size_t)w * CH] = u;
        prev = f;
    }
}

// ---------------- cumtrapz along h ----------------
__global__ void k_cumy()
{
    const int nw = blockIdx.x;
    const int n  = nw / WW;
    const int w  = nw - n * WW;
    const int c  = threadIdx.x;
    size_t base   = ((size_t)n * HWSZ + w) * CH + c;
    size_t stride = (size_t)WW * CH;
    float pf = g_ft[base], pu = g_Ux[base];
    float uy = 0.f, tt = 0.f;
    g_Uy[base] = 0.f;
    g_T[base]  = 0.f;
    for (int hh = 1; hh < HH; ++hh) {
        float f = g_ft[base + hh * stride];
        float u = g_Ux[base + hh * stride];
        uy += 0.5f * (pf + f);
        tt += 0.5f * (pu + u);
        g_Uy[base + hh * stride] = uy;
        g_T [base + hh * stride] = tt;
        pf = f; pu = u;
    }
}

// ---------------- PrRoI pooling (+ FC-stat and g_fc zeroing) ----------------
__global__ void k_pool(const float* __restrict__ props)
{
    const int p = blockIdx.x;
    const int c = threadIdx.x;
    if (p == 0) { g_fsum[c] = 0.f; g_fsq[c] = 0.f; }
    g_fc[(size_t)p * CH + c] = 0.f;     // zero for split-K fc atomics
    const float px = __ldg(&props[p * 4 + 0]);
    const float py = __ldg(&props[p * 4 + 1]);
    const float pw = __ldg(&props[p * 4 + 2]);
    const float ph = __ldg(&props[p * 4 + 3]);
    const float x1 = px * 20.f;
    const float y1 = py * 20.f;
    const float x2 = (px + pw) * 20.f;
    const float y2 = (py + ph) * 20.f;
    const float bw = (x2 - x1) * 0.25f;
    const float bh = (y2 - y1) * 0.25f;

    int   wx[5], hy[5];
    float px0[5], px1[5], py0[5], py1[5];
#pragma unroll
    for (int i = 0; i < 5; ++i) {
        float xs = fminf(fmaxf(x1 + bw * (float)i, 0.f), 35.f);
        int w0 = min((int)floorf(xs), 34);
        float sx = xs - (float)w0;
        float q = 0.5f * sx * sx;
        px1[i] = q; px0[i] = sx - q; wx[i] = w0;

        float ys = fminf(fmaxf(y1 + bh * (float)i, 0.f), 35.f);
        int h0 = min((int)floorf(ys), 34);
        float sy = ys - (float)h0;
        float r = 0.5f * sy * sy;
        py1[i] = r; py0[i] = sy - r; hy[i] = h0;
    }

    const int b = p >> 4;
    float G[5][5];
#pragma unroll
    for (int iy = 0; iy < 5; ++iy) {
#pragma unroll
        for (int ix = 0; ix < 5; ++ix) {
            size_t i00 = (((size_t)b * HH + hy[iy]) * WW + wx[ix]) * CH + c;
            size_t i01 = i00 + CH;
            size_t i10 = i00 + (size_t)WW * CH;
            size_t i11 = i10 + CH;
            G[iy][ix] = g_T[i00]
                      + g_Uy[i00] * px0[ix] + g_Uy[i01] * px1[ix]
                      + py0[iy] * (g_Ux[i00] + g_ft[i00] * px0[ix] + g_ft[i01] * px1[ix])
                      + py1[iy] * (g_Ux[i10] + g_ft[i10] * px0[ix] + g_ft[i11] * px1[ix]);
        }
    }
    const float area = bw * bh;
    const float inv  = (area > 1e-8f) ? (1.f / fmaxf(area, 1e-8f)) : 0.f;
    float* out = g_rf + (size_t)p * FCK + c * 16;
#pragma unroll
    for (int iy = 0; iy < 4; ++iy)
#pragma unroll
        for (int ix = 0; ix < 4; ++ix)
            out[iy * 4 + ix] =
                (G[iy + 1][ix + 1] - G[iy][ix + 1] - G[iy + 1][ix] + G[iy][ix]) * inv;
}

// ---------------- FC GEMM, split-K=8, atomic accumulate ----------------
__global__ void __launch_bounds__(256) k_fc(const float* __restrict__ Wfc)
{
    __shared__ float As[16][65];
    __shared__ float Bs[16][65];

    const int tid = threadIdx.x;
    const int mt  = blockIdx.x * 64;
    const int nt  = blockIdx.y * 64;
    const int kc0 = blockIdx.z * 32;      // 32 of 256 kc iterations
    const int lr  = tid >> 2;
    const int lk  = (tid & 3) * 4;
    const int tm  = tid & 15;
    const int tn  = tid >> 4;

    float acc[4][4];
#pragma unroll
    for (int i = 0; i < 4; ++i)
#pragma unroll
        for (int j = 0; j < 4; ++j) acc[i][j] = 0.f;

    for (int kc = kc0; kc < kc0 + 32; ++kc) {
        float4 av = *(const float4*)&g_rf[(size_t)(mt + lr) * FCK + kc * 16 + lk];
        float4 bv = *(const float4*)&Wfc [(size_t)(nt + lr) * FCK + kc * 16 + lk];
        __syncthreads();
        As[lk + 0][lr] = av.x; As[lk + 1][lr] = av.y;
        As[lk + 2][lr] = av.z; As[lk + 3][lr] = av.w;
        Bs[lk + 0][lr] = bv.x; Bs[lk + 1][lr] = bv.y;
        Bs[lk + 2][lr] = bv.z; Bs[lk + 3][lr] = bv.w;
        __syncthreads();
#pragma unroll
        for (int kk = 0; kk < 16; ++kk) {
            float a[4], b[4];
#pragma unroll
            for (int i = 0; i < 4; ++i) a[i] = As[kk][tm + 16 * i];
#pragma unroll
            for (int j = 0; j < 4; ++j) b[j] = Bs[kk][tn * 4 + j];
#pragma unroll
            for (int i = 0; i < 4; ++i)
#pragma unroll
                for (int j = 0; j < 4; ++j)
                    acc[i][j] = fmaf(a[i], b[j], acc[i][j]);
        }
    }
#pragma unroll
    for (int j = 0; j < 4; ++j) {
        const int c = nt + tn * 4 + j;
#pragma unroll
        for (int i = 0; i < 4; ++i) {
            const int m = mt + tm + 16 * i;
            atomicAdd(&g_fc[(size_t)m * CH + c], acc[i][j]);
        }
    }
}

// ---------------- FC bias + stats ----------------
__global__ void k_fcstat(const float* __restrict__ fcb)
{
    const int c = threadIdx.x;
    const float b = __ldg(&fcb[c]);
    float s1 = 0.f, s2 = 0.f;
#pragma unroll
    for (int r = 0; r < 16; ++r) {
        const int row = blockIdx.x * 16 + r;
        float v = g_fc[(size_t)row * CH + c] + b;
        g_fc[(size_t)row * CH + c] = v;
        s1 += v; s2 += v * v;
    }
    atomicAdd(&g_fsum[c], s1);
    atomicAdd(&g_fsq [c], s2);
}

// ---------------- FC BN + ReLU + IoU head ----------------
__global__ void k_fcbn_iou(const float* __restrict__ gm,
                           const float* __restrict__ bt,
                           const float* __restrict__ iw,
                           const float* __restrict__ ib,
                           float* __restrict__ out)
{
    __shared__ float sred[8];
    const int p = blockIdx.x;
    const int c = threadIdx.x;
    const float invN = 1.f / (float)NROI;
    float m  = g_fsum[c] * invN;
    float v  = g_fsq[c] * invN - m * m;
    float sc = rsqrtf(v + EPS_BN) * __ldg(&gm[c]);
    float sh = __ldg(&bt[c]) - m * sc;
    float x  = fmaxf(fmaf(g_fc[(size_t)p * CH + c], sc, sh), 0.f);
    float t  = x * __ldg(&iw[c]);
#pragma unroll
    for (int o = 16; o; o >>= 1) t += __shfl_xor_sync(0xffffffffu, t, o);
    if ((c & 31) == 0) sred[c >> 5] = t;
    __syncthreads();
    if (c == 0) {
        float s = 0.f;
#pragma unroll
        for (int i = 0; i < 8; ++i) s += sred[i];
        out[p] = s + __ldg(&ib[0]);
    }
}

// ---------------- launch sequence ----------------
extern "C" void kernel_launch(void* const* d_in, const int* in_sizes, int n_in,
                              void* d_out, int out_size)
{
    const float* feat  = (const float*)d_in[0];
    const float* props = (const float*)d_in[1];
    const float* c1w = (const float*)d_in[2];
    const float* c1b = (const float*)d_in[3];
    const float* b1g = (const float*)d_in[4];
    const float* b1b = (const float*)d_in[5];
    const float* c2w = (const float*)d_in[6];
    const float* c2b = (const float*)d_in[7];
    const float* b2g = (const float*)d_in[8];
    const float* b2b = (const float*)d_in[9];
    const float* c3w = (const float*)d_in[10];
    const float* c3b = (const float*)d_in[11];
    const float* b3g = (const float*)d_in[12];
    const float* b3b = (const float*)d_in[13];
    const float* fcw = (const float*)d_in[14];
    const float* fcb = (const float*)d_in[15];
    const float* fbg = (const float*)d_in[16];
    const float* fbb = (const float*)d_in[17];
    const float* iw  = (const float*)d_in[18];
    const float* ib  = (const float*)d_in[19];
    float* out = (float*)d_out;

    const int CONV_SMEM = 3 * STG_B;   // 104448 B per CTA, 2 CTAs/SM
    cudaFuncSetAttribute(k_conv_m, cudaFuncAttributeMaxDynamicSharedMemorySize, CONV_SMEM);

    const dim3 convGrid(MTOT / 128, 2);
    const int  wpBlocks = NK2;                  // 1152
    const int  spBlocks = 128 * MTOT / 256;     // 20736 (cvtA)

    // conv1  (k_wprep zeroes conv stats in block 0)
    k_wprep<<<wpBlocks, 256>>>(c1w);
    k_cvtA<<<spBlocks, 256>>>(feat);
    k_conv_m<<<convGrid, 128, CONV_SMEM>>>(c1b);
    k_bnsplit_t<<<dim3(8, NIMG, 41), dim3(32, 8)>>>(b1g, b1b);
    // conv2
    k_wprep<<<wpBlocks, 256>>>(c2w);
    k_conv_m<<<convGrid, 128, CONV_SMEM>>>(c2b);
    k_bnsplit_t<<<dim3(8, NIMG, 41), dim3(32, 8)>>>(b2g, b2b);
    // conv3
    k_wprep<<<wpBlocks, 256>>>(c3w);
    k_conv_m<<<convGrid, 128, CONV_SMEM>>>(c3b);

    // fused final BN + cumx, then cumy (integral images, NHWC)
    k_bn_cumx<<<NIMG * HH, 256>>>(b3g, b3b);
    k_cumy<<<NIMG * WW, 256>>>();

    // PrRoI pooling (zeroes FC stats + g_fc)
    k_pool<<<NROI, 256>>>(props);

    // FC (split-K=8) + bias/stats + BN + IoU
    k_fc<<<dim3(NROI / 64, CH / 64, 8), 256>>>(fcw);
    k_fcstat<<<32, 256>>>(fcb);
    k_fcbn_iou<<<NROI, 256>>>(fbg, fbb, iw, ib, out);
}

// round 15
// speedup vs baseline: 1.6958x; 1.2720x over previous
#include <cuda_runtime.h>
#include <cuda_fp16.h>
#include <cstdint>

// ---------------- problem constants ----------------
#define NIMG 32
#define CH   256
#define HH   36
#define WW   36
#define HWSZ 1296
#define MTOT (NIMG*HWSZ)   // 41472
#define KTOT (CH*9)        // 2304
#define NK2  (KTOT/2)      // 1152
#define NROI 512
#define FCK  4096
#define EPS_BN 1e-5f
#define CHW  (CH*HWSZ)

// ---------------- scratch ----------------
__device__ float    g_bufA[MTOT*CH];        // conv output, NHWC fp32
__device__ uint32_t g_aH[128*MTOT];         // activations [ci2][M] fp16x2 hi
__device__ uint32_t g_aL[128*MTOT];         // fp16x2 lo residual
__device__ uint32_t g_wb[NK2*CH];           // weights [k2][n] fp16x2 (k = tap*256+ci)
__device__ float g_ft [MTOT*CH];            // NHWC feat (pool phase)
__device__ float g_Ux [MTOT*CH];
__device__ float g_Uy [MTOT*CH];
__device__ float g_T  [MTOT*CH];
__device__ float g_rf [NROI*FCK];
__device__ float g_fc [NROI*CH];
__device__ float g_sum[CH], g_sq[CH];
__device__ float g_fsum[CH], g_fsq[CH];

// ---------------- helpers ----------------
__device__ __forceinline__ uint32_t smem_u32(const void* p) {
    uint32_t a;
    asm("{ .reg .u64 t; cvta.to.shared.u64 t, %1; cvt.u32.u64 %0, t; }" : "=r"(a) : "l"(p));
    return a;
}
__device__ __forceinline__ void hsplit(float v, uint16_t& hi, uint16_t& lo) {
    __half h = __float2half_rn(v);
    __half l = __float2half_rn(v - __half2float(h));
    hi = __half_as_ushort(h);
    lo = __half_as_ushort(l);
}
__device__ __forceinline__ uint16_t h1(float v) {
    return __half_as_ushort(__float2half_rn(v));
}
__device__ __forceinline__ void mma16(float d[4], const uint32_t a[4], const uint32_t b[2]) {
    asm volatile("mma.sync.aligned.m16n8k16.row.col.f32.f16.f16.f32 "
        "{%0,%1,%2,%3},{%4,%5,%6,%7},{%8,%9},{%0,%1,%2,%3};"
        : "+f"(d[0]), "+f"(d[1]), "+f"(d[2]), "+f"(d[3])
        : "r"(a[0]), "r"(a[1]), "r"(a[2]), "r"(a[3]), "r"(b[0]), "r"(b[1]));
}
__device__ __forceinline__ void cp4(uint32_t dst, const void* src, uint32_t sz) {
    asm volatile("cp.async.ca.shared.global [%0], [%1], 4, %2;" :: "r"(dst), "l"(src), "r"(sz));
}
__device__ __forceinline__ void cp16(uint32_t dst, const void* src) {
    asm volatile("cp.async.cg.shared.global [%0], [%1], 16;" :: "r"(dst), "l"(src));
}
#define CP_COMMIT() asm volatile("cp.async.commit_group;" ::: "memory")
#define CP_WAIT1()  asm volatile("cp.async.wait_group 1;"  ::: "memory")

// ---------------- weight prep: [k2][n] fp16-pair + conv-stat zeroing ----------------
__global__ void k_wprep(const float* __restrict__ W) {
    int idx = blockIdx.x * 256 + threadIdx.x;   // idx = k2*256 + n
    if (blockIdx.x == 0) {
        g_sum[threadIdx.x] = 0.f;
        g_sq [threadIdx.x] = 0.f;
    }
    int n   = idx & 255;
    int k2  = idx >> 8;
    int ci2 = k2 & 127;
    int tap = k2 >> 7;
    float v0 = __ldg(&W[(size_t)n * KTOT + (2 * ci2)     * 9 + tap]);
    float v1 = __ldg(&W[(size_t)n * KTOT + (2 * ci2 + 1) * 9 + tap]);
    g_wb[idx] = ((uint32_t)h1(v1) << 16) | h1(v0);
}

// ---------------- conv1 input prep: NCHW feat -> [ci2][M] fp16-pair split ----------------
__global__ void k_cvtA(const float* __restrict__ feat) {
    int i   = blockIdx.x * 256 + threadIdx.x;   // i = ci2*MTOT + m
    int ci2 = i / MTOT;
    int m   = i - ci2 * MTOT;
    int nimg = m / HWSZ;
    int hw   = m - nimg * HWSZ;
    const size_t s = ((size_t)nimg * CH + 2 * ci2) * HWSZ + hw;
    float v0 = __ldg(&feat[s]);
    float v1 = __ldg(&feat[s + HWSZ]);
    uint16_t h0, l0, hh1, l1;
    hsplit(v0, h0, l0);
    hsplit(v1, hh1, l1);
    g_aH[i] = ((uint32_t)hh1 << 16) | h0;
    g_aL[i] = ((uint32_t)l1 << 16) | l0;
}

// ===== 3-stage pipelined fp16x2 m16n8k16 implicit-GEMM conv, 2 CTAs/SM =====
// A exact (hi+lo fp16), B single fp16. 2 MMA passes per tile.
// Stage (words): AsH[16][136] AsL[16][136] Bs[16][136] = 26112 B; 3 stages = 78336 B.
#define NCHNK 72
#define STG_W 6528
#define STG_B 26112

__global__ void __launch_bounds__(128, 2) k_conv_m(const float* __restrict__ bias)
{
    extern __shared__ uint32_t dynu[];
    __shared__ float sRed1[128], sRed2[128];
    const uint32_t sb = smem_u32(dynu);

    const int tid  = threadIdx.x;
    const int lane = tid & 31, wid = tid >> 5;
    const int mt   = blockIdx.x * 128, nt = blockIdx.y * 128;
    const int wm   = (wid >> 1) * 64, wn = (wid & 1) * 64;
    const int g    = lane >> 2, c0 = lane & 3;

    sRed1[tid] = 0.f; sRed2[tid] = 0.f;

    // A-fill mapping: thread owns m = mt + tid; 16 k2 per chunk, stride MTOT
    const int mA    = mt + tid;
    const int nimgA = mA / HWSZ;
    const int remA  = mA - nimgA * HWSZ;
    const int hA    = remA / WW;
    const int wA    = remA - hA * WW;
    const int aimg  = nimgA * HWSZ;

    // B-fill mapping: rows bkrow+4j, 16B of n
    const int bkrow = tid >> 5;            // 0..3
    const int bn4   = (tid & 31) * 4;      // word offset in n

    float acc[4][8][4];
#pragma unroll
    for (int a = 0; a < 4; ++a)
#pragma unroll
        for (int b = 0; b < 8; ++b)
#pragma unroll
            for (int c = 0; c < 4; ++c) acc[a][b][c] = 0.f;

    auto fillA = [&](int st, int ch, int half) {
        const int tap = ch >> 3, cc = ch & 7;
        const int hh = hA + tap / 3 - 1, ww = wA + tap % 3 - 1;
        const bool valid = ((unsigned)hh < HH) && ((unsigned)ww < WW);
        const uint32_t sz = valid ? 4u : 0u;
        const uint32_t* p = (half ? g_aL : g_aH)
                          + (size_t)(cc * 16) * MTOT + aimg + (valid ? hh * WW + ww : 0);
        uint32_t d = sb + st * STG_B + half * 8704 + tid * 4;
#pragma unroll
        for (int i = 0; i < 16; ++i) {
            cp4(d, p, sz);
            p += MTOT; d += 544;
        }
    };
    auto fillB = [&](int st, int ch) {
        const int tap = ch >> 3, cc = ch & 7;
        const int kb2 = tap * 128 + cc * 16;
        uint32_t d = sb + st * STG_B + 17408 + bkrow * 544 + bn4 * 4;
#pragma unroll
        for (int j = 0; j < 4; ++j)
            cp16(d + j * 2176, g_wb + (size_t)(kb2 + bkrow + j * 4) * 256 + nt + bn4);
    };

    // prologue: stages 0 and 1 (chunks 0 and 1)
    fillA(0, 0, 0); fillA(0, 0, 1); fillB(0, 0); CP_COMMIT();
    fillA(1, 1, 0); fillA(1, 1, 1); fillB(1, 1); CP_COMMIT();

    int stc = 0, stf = 2;
    for (int ch = 0; ch < NCHNK; ++ch) {
        CP_WAIT1();
        __syncthreads();
        const bool pf = (ch + 2) < NCHNK;
        const uint32_t* base = dynu + stc * STG_W;
        const uint32_t* AsH = base;
        const uint32_t* AsL = base + 2176;
        const uint32_t* Bs  = base + 4352;
#pragma unroll
        for (int kk = 0; kk < 2; ++kk) {
            if (pf) {
                if (kk == 0) { fillA(stf, ch + 2, 0); fillA(stf, ch + 2, 1); }
                else         { fillB(stf, ch + 2); }
            }
            const int r0 = (kk * 8 + c0) * 136;
            const int r1 = r0 + 4 * 136;
            uint32_t ah[4][4], al[4][4], bh[8][2];
#pragma unroll
            for (int mf = 0; mf < 4; ++mf) {
                const int col = wm + mf * 16 + g;
                ah[mf][0] = AsH[r0 + col];
                ah[mf][1] = AsH[r0 + col + 8];
                ah[mf][2] = AsH[r1 + col];
                ah[mf][3] = AsH[r1 + col + 8];
                al[mf][0] = AsL[r0 + col];
                al[mf][1] = AsL[r0 + col + 8];
                al[mf][2] = AsL[r1 + col];
                al[mf][3] = AsL[r1 + col + 8];
            }
#pragma unroll
            for (int nf = 0; nf < 8; ++nf) {
                const int q0 = r0 + wn + nf * 8 + g;
                bh[nf][0] = Bs[q0];
                bh[nf][1] = Bs[q0 + 4 * 136];
            }
#pragma unroll
            for (int mf = 0; mf < 4; ++mf)
#pragma unroll
                for (int nf = 0; nf < 8; ++nf)
                    mma16(acc[mf][nf], ah[mf], bh[nf]);
#pragma unroll
            for (int mf = 0; mf < 4; ++mf)
#pragma unroll
                for (int nf = 0; nf < 8; ++nf)
                    mma16(acc[mf][nf], al[mf], bh[nf]);
        }
        CP_COMMIT();
        stc = (stc == 2) ? 0 : stc + 1;
        stf = (stf == 2) ? 0 : stf + 1;
    }

    // ---------------- epilogue: bias, NHWC store (coalesced), fused stats ----------------
    float s1[16], s2[16];
#pragma unroll
    for (int i = 0; i < 16; ++i) { s1[i] = 0.f; s2[i] = 0.f; }

#pragma unroll
    for (int mf = 0; mf < 4; ++mf) {
#pragma unroll
        for (int rr = 0; rr < 2; ++rr) {
            const int m = mt + wm + mf * 16 + g + rr * 8;
            float* orow = g_bufA + (size_t)m * CH;
#pragma unroll
            for (int nf = 0; nf < 8; ++nf) {
                const int c = nt + wn + nf * 8 + c0 * 2;
                const float v0 = acc[mf][nf][rr * 2]     + __ldg(&bias[c]);
                const float v1 = acc[mf][nf][rr * 2 + 1] + __ldg(&bias[c + 1]);
                *(float2*)(orow + c) = make_float2(v0, v1);
                s1[nf * 2]     += v0; s2[nf * 2]     += v0 * v0;
                s1[nf * 2 + 1] += v1; s2[nf * 2 + 1] += v1 * v1;
            }
        }
    }
    __syncthreads();
#pragma unroll
    for (int nf = 0; nf < 8; ++nf) {
        const int cl = wn + nf * 8 + c0 * 2;
        atomicAdd(&sRed1[cl],     s1[nf * 2]);
        atomicAdd(&sRed2[cl],     s2[nf * 2]);
        atomicAdd(&sRed1[cl + 1], s1[nf * 2 + 1]);
        atomicAdd(&sRed2[cl + 1], s2[nf * 2 + 1]);
    }
    __syncthreads();
    atomicAdd(&g_sum[nt + tid], sRed1[tid]);
    atomicAdd(&g_sq [nt + tid], sRed2[tid]);
}

// ---------------- BN+ReLU+split via 32x32 smem transpose: NHWC -> [ci2][M] ----------------
__global__ void k_bnsplit_t(const float* __restrict__ gm,
                            const float* __restrict__ bt)
{
    __shared__ float s[32][33];
    __shared__ float ssc[32], ssh[32];
    const int cb = blockIdx.x;
    const int n  = blockIdx.y;
    const int pb = blockIdx.z;
    const int tx = threadIdx.x, ty = threadIdx.y;
    const int tid = ty * 32 + tx;
    const float invN = 1.0f / (float)MTOT;

    if (tid < 32) {
        const int c = cb * 32 + tid;
        float m = g_sum[c] * invN;
        float v = g_sq[c] * invN - m * m;
        float sc = rsqrtf(v + EPS_BN) * __ldg(&gm[c]);
        ssc[tid] = sc;
        ssh[tid] = __ldg(&bt[c]) - m * sc;
    }
    __syncthreads();

    const int p0 = pb * 32;
#pragma unroll
    for (int yy = 0; yy < 4; ++yy) {
        const int p = p0 + ty + yy * 8;
        float x = (p < HWSZ)
                ? g_bufA[((size_t)n * HWSZ + p) * CH + cb * 32 + tx] : 0.f;
        s[tx][ty + yy * 8] = fmaxf(fmaf(x, ssc[tx], ssh[tx]), 0.f);
    }
    __syncthreads();
#pragma unroll
    for (int yy = 0; yy < 2; ++yy) {
        const int ci2l = ty + yy * 8;       // 0..15
        const int p = p0 + tx;
        if (p < HWSZ) {
            float y0 = s[2 * ci2l][tx];
            float y1 = s[2 * ci2l + 1][tx];
            uint16_t h0, l0, hh1, l1;
            hsplit(y0, h0, l0);
            hsplit(y1, hh1, l1);
            const size_t i = (size_t)(cb * 16 + ci2l) * MTOT + (size_t)n * HWSZ + p;
            g_aH[i] = ((uint32_t)hh1 << 16) | h0;
            g_aL[i] = ((uint32_t)l1 << 16) | l0;
        }
    }
}

// ---------------- fused final BN + ReLU + cumtrapz along w ----------------
__global__ void k_bn_cumx(const float* __restrict__ gm,
                          const float* __restrict__ bt)
{
    const int nh = blockIdx.x;
    const int c  = threadIdx.x;
    const float invN = 1.0f / (float)MTOT;
    float m  = g_sum[c] * invN;
    float v  = g_sq[c] * invN - m * m;
    float sc = rsqrtf(v + EPS_BN) * __ldg(&gm[c]);
    float sh = __ldg(&bt[c]) - m * sc;

    size_t base = ((size_t)nh * WW) * CH + c;
    float prev = fmaxf(fmaf(g_bufA[base], sc, sh), 0.f);
    g_ft[base] = prev;
    g_Ux[base] = 0.f;
    float u = 0.f;
    for (int w = 1; w < WW; ++w) {
        float f = fmaxf(fmaf(g_bufA[base + (size_t)w * CH], sc, sh), 0.f);
        u += 0.5f * (prev + f);
        g_ft[base + (size_t)w * CH] = f;
        g_Ux[base + (size_t)w * CH] = u;
        prev = f;
    }
}

// ---------------- cumtrapz along h ----------------
__global__ void k_cumy()
{
    const int nw = blockIdx.x;
    const int n  = nw / WW;
    const int w  = nw - n * WW;
    const int c  = threadIdx.x;
    size_t base   = ((size_t)n * HWSZ + w) * CH + c;
    size_t stride = (size_t)WW * CH;
    float pf = g_ft[base], pu = g_Ux[base];
    float uy = 0.f, tt = 0.f;
    g_Uy[base] = 0.f;
    g_T[base]  = 0.f;
    for (int hh = 1; hh < HH; ++hh) {
        float f = g_ft[base + hh * stride];
        float u = g_Ux[base + hh * stride];
        uy += 0.5f * (pf + f);
        tt += 0.5f * (pu + u);
        g_Uy[base + hh * stride] = uy;
        g_T [base + hh * stride] = tt;
        pf = f; pu = u;
    }
}

// ---------------- PrRoI pooling (+ FC-stat and g_fc zeroing) ----------------
__global__ void k_pool(const float* __restrict__ props)
{
    const int p = blockIdx.x;
    const int c = threadIdx.x;
    if (p == 0) { g_fsum[c] = 0.f; g_fsq[c] = 0.f; }
    g_fc[(size_t)p * CH + c] = 0.f;     // zero for split-K fc atomics
    const float px = __ldg(&props[p * 4 + 0]);
    const float py = __ldg(&props[p * 4 + 1]);
    const float pw = __ldg(&props[p * 4 + 2]);
    const float ph = __ldg(&props[p * 4 + 3]);
    const float x1 = px * 20.f;
    const float y1 = py * 20.f;
    const float x2 = (px + pw) * 20.f;
    const float y2 = (py + ph) * 20.f;
    const float bw = (x2 - x1) * 0.25f;
    const float bh = (y2 - y1) * 0.25f;

    int   wx[5], hy[5];
    float px0[5], px1[5], py0[5], py1[5];
#pragma unroll
    for (int i = 0; i < 5; ++i) {
        float xs = fminf(fmaxf(x1 + bw * (float)i, 0.f), 35.f);
        int w0 = min((int)floorf(xs), 34);
        float sx = xs - (float)w0;
        float q = 0.5f * sx * sx;
        px1[i] = q; px0[i] = sx - q; wx[i] = w0;

        float ys = fminf(fmaxf(y1 + bh * (float)i, 0.f), 35.f);
        int h0 = min((int)floorf(ys), 34);
        float sy = ys - (float)h0;
        float r = 0.5f * sy * sy;
        py1[i] = r; py0[i] = sy - r; hy[i] = h0;
    }

    const int b = p >> 4;
    float G[5][5];
#pragma unroll
    for (int iy = 0; iy < 5; ++iy) {
#pragma unroll
        for (int ix = 0; ix < 5; ++ix) {
            size_t i00 = (((size_t)b * HH + hy[iy]) * WW + wx[ix]) * CH + c;
            size_t i01 = i00 + CH;
            size_t i10 = i00 + (size_t)WW * CH;
            size_t i11 = i10 + CH;
            G[iy][ix] = g_T[i00]
                      + g_Uy[i00] * px0[ix] + g_Uy[i01] * px1[ix]
                      + py0[iy] * (g_Ux[i00] + g_ft[i00] * px0[ix] + g_ft[i01] * px1[ix])
                      + py1[iy] * (g_Ux[i10] + g_ft[i10] * px0[ix] + g_ft[i11] * px1[ix]);
        }
    }
    const float area = bw * bh;
    const float inv  = (area > 1e-8f) ? (1.f / fmaxf(area, 1e-8f)) : 0.f;
    float* out = g_rf + (size_t)p * FCK + c * 16;
#pragma unroll
    for (int iy = 0; iy < 4; ++iy)
#pragma unroll
        for (int ix = 0; ix < 4; ++ix)
            out[iy * 4 + ix] =
                (G[iy + 1][ix + 1] - G[iy][ix + 1] - G[iy + 1][ix] + G[iy][ix]) * inv;
}

// ---------------- FC GEMM, split-K=8, atomic accumulate ----------------
__global__ void __launch_bounds__(256) k_fc(const float* __restrict__ Wfc)
{
    __shared__ float As[16][65];
    __shared__ float Bs[16][65];

    const int tid = threadIdx.x;
    const int mt  = blockIdx.x * 64;
    const int nt  = blockIdx.y * 64;
    const int kc0 = blockIdx.z * 32;
    const int lr  = tid >> 2;
    const int lk  = (tid & 3) * 4;
    const int tm  = tid & 15;
    const int tn  = tid >> 4;

    float acc[4][4];
#pragma unroll
    for (int i = 0; i < 4; ++i)
#pragma unroll
        for (int j = 0; j < 4; ++j) acc[i][j] = 0.f;

    for (int kc = kc0; kc < kc0 + 32; ++kc) {
        float4 av = *(const float4*)&g_rf[(size_t)(mt + lr) * FCK + kc * 16 + lk];
        float4 bv = *(const float4*)&Wfc [(size_t)(nt + lr) * FCK + kc * 16 + lk];
        __syncthreads();
        As[lk + 0][lr] = av.x; As[lk + 1][lr] = av.y;
        As[lk + 2][lr] = av.z; As[lk + 3][lr] = av.w;
        Bs[lk + 0][lr] = bv.x; Bs[lk + 1][lr] = bv.y;
        Bs[lk + 2][lr] = bv.z; Bs[lk + 3][lr] = bv.w;
        __syncthreads();
#pragma unroll
        for (int kk = 0; kk < 16; ++kk) {
            float a[4], b[4];
#pragma unroll
            for (int i = 0; i < 4; ++i) a[i] = As[kk][tm + 16 * i];
#pragma unroll
            for (int j = 0; j < 4; ++j) b[j] = Bs[kk][tn * 4 + j];
#pragma unroll
            for (int i = 0; i < 4; ++i)
#pragma unroll
                for (int j = 0; j < 4; ++j)
                    acc[i][j] = fmaf(a[i], b[j], acc[i][j]);
        }
    }
#pragma unroll
    for (int j = 0; j < 4; ++j) {
        const int c = nt + tn * 4 + j;
#pragma unroll
        for (int i = 0; i < 4; ++i) {
            const int m = mt + tm + 16 * i;
            atomicAdd(&g_fc[(size_t)m * CH + c], acc[i][j]);
        }
    }
}

// ---------------- FC bias + stats ----------------
__global__ void k_fcstat(const float* __restrict__ fcb)
{
    const int c = threadIdx.x;
    const float b = __ldg(&fcb[c]);
    float s1 = 0.f, s2 = 0.f;
#pragma unroll
    for (int r = 0; r < 16; ++r) {
        const int row = blockIdx.x * 16 + r;
        float v = g_fc[(size_t)row * CH + c] + b;
        g_fc[(size_t)row * CH + c] = v;
        s1 += v; s2 += v * v;
    }
    atomicAdd(&g_fsum[c], s1);
    atomicAdd(&g_fsq [c], s2);
}

// ---------------- FC BN + ReLU + IoU head ----------------
__global__ void k_fcbn_iou(const float* __restrict__ gm,
                           const float* __restrict__ bt,
                           const float* __restrict__ iw,
                           const float* __restrict__ ib,
                           float* __restrict__ out)
{
    __shared__ float sred[8];
    const int p = blockIdx.x;
    const int c = threadIdx.x;
    const float invN = 1.f / (float)NROI;
    float m  = g_fsum[c] * invN;
    float v  = g_fsq[c] * invN - m * m;
    float sc = rsqrtf(v + EPS_BN) * __ldg(&gm[c]);
    float sh = __ldg(&bt[c]) - m * sc;
    float x  = fmaxf(fmaf(g_fc[(size_t)p * CH + c], sc, sh), 0.f);
    float t  = x * __ldg(&iw[c]);
#pragma unroll
    for (int o = 16; o; o >>= 1) t += __shfl_xor_sync(0xffffffffu, t, o);
    if ((c & 31) == 0) sred[c >> 5] = t;
    __syncthreads();
    if (c == 0) {
        float s = 0.f;
#pragma unroll
        for (int i = 0; i < 8; ++i) s += sred[i];
        out[p] = s + __ldg(&ib[0]);
    }
}

// ---------------- launch sequence ----------------
extern "C" void kernel_launch(void* const* d_in, const int* in_sizes, int n_in,
                              void* d_out, int out_size)
{
    const float* feat  = (const float*)d_in[0];
    const float* props = (const float*)d_in[1];
    const float* c1w = (const float*)d_in[2];
    const float* c1b = (const float*)d_in[3];
    const float* b1g = (const float*)d_in[4];
    const float* b1b = (const float*)d_in[5];
    const float* c2w = (const float*)d_in[6];
    const float* c2b = (const float*)d_in[7];
    const float* b2g = (const float*)d_in[8];
    const float* b2b = (const float*)d_in[9];
    const float* c3w = (const float*)d_in[10];
    const float* c3b = (const float*)d_in[11];
    const float* b3g = (const float*)d_in[12];
    const float* b3b = (const float*)d_in[13];
    const float* fcw = (const float*)d_in[14];
    const float* fcb = (const float*)d_in[15];
    const float* fbg = (const float*)d_in[16];
    const float* fbb = (const float*)d_in[17];
    const float* iw  = (const float*)d_in[18];
    const float* ib  = (const float*)d_in[19];
    float* out = (float*)d_out;

    const int CONV_SMEM = 3 * STG_B;   // 78336 B per CTA, 2 CTAs/SM
    cudaFuncSetAttribute(k_conv_m, cudaFuncAttributeMaxDynamicSharedMemorySize, CONV_SMEM);

    const dim3 convGrid(MTOT / 128, 2);
    const int  wpBlocks = NK2;                  // 1152
    const int  spBlocks = 128 * MTOT / 256;     // 20736 (cvtA)

    // conv1  (k_wprep zeroes conv stats in block 0)
    k_wprep<<<wpBlocks, 256>>>(c1w);
    k_cvtA<<<spBlocks, 256>>>(feat);
    k_conv_m<<<convGrid, 128, CONV_SMEM>>>(c1b);
    k_bnsplit_t<<<dim3(8, NIMG, 41), dim3(32, 8)>>>(b1g, b1b);
    // conv2
    k_wprep<<<wpBlocks, 256>>>(c2w);
    k_conv_m<<<convGrid, 128, CONV_SMEM>>>(c2b);
    k_bnsplit_t<<<dim3(8, NIMG, 41), dim3(32, 8)>>>(b2g, b2b);
    // conv3
    k_wprep<<<wpBlocks, 256>>>(c3w);
    k_conv_m<<<convGrid, 128, CONV_SMEM>>>(c3b);

    // fused final BN + cumx, then cumy (integral images, NHWC)
    k_bn_cumx<<<NIMG * HH, 256>>>(b3g, b3b);
    k_cumy<<<NIMG * WW, 256>>>();

    // PrRoI pooling (zeroes FC stats + g_fc)
    k_pool<<<NROI, 256>>>(props);

    // FC (split-K=8) + bias/stats + BN + IoU
    k_fc<<<dim3(NROI / 64, CH / 64, 8), 256>>>(fcw);
    k_fcstat<<<32, 256>>>(fcb);
    k_fcbn_iou<<<NROI, 256>>>(fbg, fbb, iw, ib, out);
}